// round 1
// baseline (speedup 1.0000x reference)
#include <cuda_runtime.h>
#include <math.h>

#define BS_  2
#define SEQ  2048
#define EMB  1024
#define NH   16
#define HD   64
#define MROWS (BS_*SEQ)   // 4096

// Scratch (allocation-free rule: __device__ globals)
__device__ float g_q[(size_t)BS_*NH*SEQ*HD];   // [B,H,S,D] 16MB
__device__ float g_k[(size_t)BS_*NH*SEQ*HD];
__device__ float g_v[(size_t)BS_*NH*SEQ*HD];
__device__ float g_att[(size_t)BS_*SEQ*EMB];   // [B,S,E] attention output

// ---------------------------------------------------------------------------
// GEMM: C = A(MxK) @ B^T(NxK) + bias.  mode 0: scatter to [B,H,S,D]; mode 1: row-major.
// 128x128 tile, K-step 8, 256 threads, 8x8 microtile.
// ---------------------------------------------------------------------------
__global__ __launch_bounds__(256) void gemm_nt(const float* __restrict__ A,
                                               const float* __restrict__ B,
                                               const float* __restrict__ bias,
                                               float* __restrict__ C,
                                               int mode)
{
    __shared__ float As[8][132];
    __shared__ float Bs[8][132];

    const int tid = threadIdx.x;
    const int tx  = tid & 15;
    const int ty  = tid >> 4;
    const int bm  = blockIdx.y * 128;
    const int bn  = blockIdx.x * 128;

    const int lr = tid >> 1;          // 0..127
    const int lk = (tid & 1) * 4;     // 0 or 4
    const float* Ap = A + (size_t)(bm + lr) * EMB + lk;
    const float* Bp = B + (size_t)(bn + lr) * EMB + lk;

    float acc[8][8];
    #pragma unroll
    for (int i = 0; i < 8; i++)
        #pragma unroll
        for (int j = 0; j < 8; j++) acc[i][j] = 0.f;

    for (int k0 = 0; k0 < EMB; k0 += 8) {
        float4 a4 = *(const float4*)(Ap + k0);
        float4 b4 = *(const float4*)(Bp + k0);
        __syncthreads();
        As[lk+0][lr] = a4.x; As[lk+1][lr] = a4.y; As[lk+2][lr] = a4.z; As[lk+3][lr] = a4.w;
        Bs[lk+0][lr] = b4.x; Bs[lk+1][lr] = b4.y; Bs[lk+2][lr] = b4.z; Bs[lk+3][lr] = b4.w;
        __syncthreads();

        #pragma unroll
        for (int k = 0; k < 8; k++) {
            float4 a0 = *(const float4*)&As[k][ty*8];
            float4 a1 = *(const float4*)&As[k][ty*8+4];
            float4 b0 = *(const float4*)&Bs[k][tx*8];
            float4 b1 = *(const float4*)&Bs[k][tx*8+4];
            float ar[8] = {a0.x,a0.y,a0.z,a0.w,a1.x,a1.y,a1.z,a1.w};
            float br[8] = {b0.x,b0.y,b0.z,b0.w,b1.x,b1.y,b1.z,b1.w};
            #pragma unroll
            for (int i = 0; i < 8; i++)
                #pragma unroll
                for (int j = 0; j < 8; j++)
                    acc[i][j] += ar[i] * br[j];
        }
    }

    #pragma unroll
    for (int i = 0; i < 8; i++) {
        const int row = bm + ty*8 + i;
        #pragma unroll
        for (int j = 0; j < 8; j++) {
            const int col = bn + tx*8 + j;
            const float v = acc[i][j] + bias[col];
            if (mode == 0) {
                const int bb = row >> 11, s = row & 2047;
                const int h  = col >> 6,  d = col & 63;
                C[(((size_t)bb*NH + h)*SEQ + s)*HD + d] = v;
            } else {
                C[(size_t)row*EMB + col] = v;
            }
        }
    }
}

// ---------------------------------------------------------------------------
// RoPE applied in place to g_q and g_k ([B,H,S,D] layout). One thread per
// (bh, s, d<32) pair — handles both halves, both tensors.
// ---------------------------------------------------------------------------
__global__ __launch_bounds__(256) void rope_kernel()
{
    const int idx = blockIdx.x * 256 + threadIdx.x;
    const int total = BS_*NH*SEQ*32;
    if (idx >= total) return;
    const int d  = idx & 31;
    const int s  = (idx >> 5) & (SEQ-1);
    const int bh = idx >> 16;

    // inv_freq = 10000^(-2d/64) = 2^(-d/32 * log2(10000))
    const float inv = exp2f(-(float)d * (13.287712379549449f / 32.0f));
    const float ang = (float)s * inv;
    float sn, cs;
    sincosf(ang, &sn, &cs);

    const size_t base = ((size_t)bh*SEQ + s)*HD;
    float q1 = g_q[base+d], q2 = g_q[base+d+32];
    g_q[base+d]    = q1*cs - q2*sn;
    g_q[base+d+32] = q2*cs + q1*sn;
    float k1 = g_k[base+d], k2 = g_k[base+d+32];
    g_k[base+d]    = k1*cs - k2*sn;
    g_k[base+d+32] = k2*cs + k1*sn;
}

// ---------------------------------------------------------------------------
// Flash attention, fp32, causal. 64x64 tiles, 256 threads (16x16), 4x4
// microtiles. Smem: Qs[d][r], Ks[d][t] (aliased by Ps[t][r]), Vs[t][d].
// ---------------------------------------------------------------------------
#define ATS 68
#define ATT_SMEM (3 * 64 * ATS * 4)

extern __shared__ float att_smem[];

__global__ __launch_bounds__(256) void attn_kernel(float* __restrict__ out)
{
    float* Qs = att_smem;              // [64][ATS], d-major
    float* Ks = Qs + 64*ATS;           // [64][ATS], d-major; aliased as Ps after scores
    float* Vs = Ks + 64*ATS;           // [64][ATS], t-major
    float* Ps = Ks;

    const int tid = threadIdx.x;
    const int tx  = tid & 15;
    const int ty  = tid >> 4;
    const int qt  = gridDim.x - 1 - blockIdx.x;   // long blocks first
    const int bh  = blockIdx.y;
    const int b   = bh >> 4;
    const int h   = bh & 15;

    const float* Qg = g_q + (size_t)bh*SEQ*HD + (size_t)qt*64*HD;
    const float* Kg = g_k + (size_t)bh*SEQ*HD;
    const float* Vg = g_v + (size_t)bh*SEQ*HD;

    // load Q tile transposed: Qs[d][r]
    #pragma unroll
    for (int i = 0; i < 16; i++) {
        const int lin = tid + 256*i;
        const int r = lin >> 6, d = lin & 63;
        Qs[d*ATS + r] = Qg[r*HD + d];
    }

    float m[4], l[4], of[4][4];
    #pragma unroll
    for (int i = 0; i < 4; i++) {
        m[i] = -INFINITY; l[i] = 0.f;
        #pragma unroll
        for (int j = 0; j < 4; j++) of[i][j] = 0.f;
    }

    const float SCL = 0.125f * 1.44269504088896340736f; // 1/sqrt(64) * log2(e)

    for (int j = 0; j <= qt; j++) {
        __syncthreads();   // previous iter's readers of Ks/Vs/Ps done
        #pragma unroll
        for (int i = 0; i < 16; i++) {
            const int lin = tid + 256*i;
            const int t = lin >> 6, d = lin & 63;
            Ks[d*ATS + t] = Kg[(j*64 + t)*HD + d];
            Vs[t*ATS + d] = Vg[(j*64 + t)*HD + d];
        }
        __syncthreads();

        // S = Q K^T (scaled into log2 domain)
        float sf[4][4];
        #pragma unroll
        for (int i = 0; i < 4; i++)
            #pragma unroll
            for (int jj = 0; jj < 4; jj++) sf[i][jj] = 0.f;

        #pragma unroll 16
        for (int d = 0; d < 64; d++) {
            float4 qa = *(const float4*)&Qs[d*ATS + ty*4];
            float4 kb = *(const float4*)&Ks[d*ATS + tx*4];
            float ar[4] = {qa.x,qa.y,qa.z,qa.w};
            float br[4] = {kb.x,kb.y,kb.z,kb.w};
            #pragma unroll
            for (int i = 0; i < 4; i++)
                #pragma unroll
                for (int jj = 0; jj < 4; jj++)
                    sf[i][jj] += ar[i]*br[jj];
        }

        const bool diag = (j == qt);
        #pragma unroll
        for (int i = 0; i < 4; i++)
            #pragma unroll
            for (int jj = 0; jj < 4; jj++) {
                float s = sf[i][jj] * SCL;
                if (diag && (tx*4 + jj > ty*4 + i)) s = -INFINITY;
                sf[i][jj] = s;
            }

        // online softmax (rows split over 16 lanes: same-ty half-warp)
        #pragma unroll
        for (int i = 0; i < 4; i++) {
            float rmax = fmaxf(fmaxf(sf[i][0], sf[i][1]), fmaxf(sf[i][2], sf[i][3]));
            #pragma unroll
            for (int o = 8; o >= 1; o >>= 1)
                rmax = fmaxf(rmax, __shfl_xor_sync(0xffffffffu, rmax, o));
            const float mn = fmaxf(m[i], rmax);
            const float alpha = exp2f(m[i] - mn);
            float rs = 0.f;
            #pragma unroll
            for (int jj = 0; jj < 4; jj++) {
                const float p = exp2f(sf[i][jj] - mn);
                sf[i][jj] = p;
                rs += p;
            }
            #pragma unroll
            for (int o = 8; o >= 1; o >>= 1)
                rs += __shfl_xor_sync(0xffffffffu, rs, o);
            l[i] = l[i]*alpha + rs;
            m[i] = mn;
            #pragma unroll
            for (int jj = 0; jj < 4; jj++) of[i][jj] *= alpha;
        }

        __syncthreads();   // all done reading Ks; safe to alias as Ps
        #pragma unroll
        for (int jj = 0; jj < 4; jj++) {
            float4 pv = make_float4(sf[0][jj], sf[1][jj], sf[2][jj], sf[3][jj]);
            *(float4*)&Ps[(tx*4 + jj)*ATS + ty*4] = pv;
        }
        __syncthreads();

        // O += P V
        #pragma unroll 16
        for (int t = 0; t < 64; t++) {
            float4 pa = *(const float4*)&Ps[t*ATS + ty*4];
            float4 vb = *(const float4*)&Vs[t*ATS + tx*4];
            float pr[4] = {pa.x,pa.y,pa.z,pa.w};
            float vr[4] = {vb.x,vb.y,vb.z,vb.w};
            #pragma unroll
            for (int i = 0; i < 4; i++)
                #pragma unroll
                for (int jj = 0; jj < 4; jj++)
                    of[i][jj] += pr[i]*vr[jj];
        }
    }

    // epilogue: write [B,S,E] layout
    #pragma unroll
    for (int i = 0; i < 4; i++) {
        const int r = qt*64 + ty*4 + i;
        const float inv = 1.f / l[i];
        float4 o4 = make_float4(of[i][0]*inv, of[i][1]*inv, of[i][2]*inv, of[i][3]*inv);
        *(float4*)&out[((size_t)b*SEQ + r)*EMB + (size_t)h*64 + tx*4] = o4;
    }
}

// ---------------------------------------------------------------------------
extern "C" void kernel_launch(void* const* d_in, const int* in_sizes, int n_in,
                              void* d_out, int out_size)
{
    const float* query = (const float*)d_in[0];
    const float* key   = (const float*)d_in[1];
    const float* value = (const float*)d_in[2];
    const float* Wq    = (const float*)d_in[3];
    const float* bq    = (const float*)d_in[4];
    const float* Wk    = (const float*)d_in[5];
    const float* bk    = (const float*)d_in[6];
    const float* Wv    = (const float*)d_in[7];
    const float* bv    = (const float*)d_in[8];
    const float* Wo    = (const float*)d_in[9];
    const float* bo    = (const float*)d_in[10];

    float *pq, *pk, *pv, *pa;
    cudaGetSymbolAddress((void**)&pq, g_q);
    cudaGetSymbolAddress((void**)&pk, g_k);
    cudaGetSymbolAddress((void**)&pv, g_v);
    cudaGetSymbolAddress((void**)&pa, g_att);

    cudaFuncSetAttribute(attn_kernel,
                         cudaFuncAttributeMaxDynamicSharedMemorySize, ATT_SMEM);

    dim3 gg(EMB/128, MROWS/128);   // 8 x 32
    gemm_nt<<<gg, 256>>>(query, Wq, bq, pq, 0);
    gemm_nt<<<gg, 256>>>(key,   Wk, bk, pk, 0);
    gemm_nt<<<gg, 256>>>(value, Wv, bv, pv, 0);

    rope_kernel<<<(BS_*NH*SEQ*32)/256, 256>>>();

    attn_kernel<<<dim3(SEQ/64, BS_*NH), 256, ATT_SMEM>>>(pa);

    gemm_nt<<<gg, 256>>>(pa, Wo, bo, (float*)d_out, 1);
}

// round 5
// speedup vs baseline: 1.7810x; 1.7810x over previous
#include <cuda_runtime.h>
#include <cuda_bf16.h>
#include <math.h>
#include <stdint.h>

#define BS_  2
#define SEQ  2048
#define EMB  1024
#define NH   16
#define HD   64
#define MROWS (BS_*SEQ)   // 4096

// ------------------------- scratch (__device__ globals) ---------------------
__device__ float g_q[(size_t)BS_*NH*SEQ*HD];   // [B,H,S,D]
__device__ float g_k[(size_t)BS_*NH*SEQ*HD];
__device__ float g_v[(size_t)BS_*NH*SEQ*HD];
__device__ float g_att[(size_t)BS_*SEQ*EMB];   // [B,S,E]
__device__ __nv_bfloat16 g_ahi[(size_t)MROWS*EMB];
__device__ __nv_bfloat16 g_alo[(size_t)MROWS*EMB];
__device__ __nv_bfloat16 g_whi[(size_t)EMB*EMB];
__device__ __nv_bfloat16 g_wlo[(size_t)EMB*EMB];

// ------------------------- helpers ------------------------------------------
__device__ __forceinline__ uint32_t smem_u32(const void* p) {
    uint32_t a;
    asm("{ .reg .u64 t; cvta.to.shared.u64 t, %1; cvt.u32.u64 %0, t; }"
        : "=r"(a) : "l"(p));
    return a;
}
#define CP16(dst, src) \
    asm volatile("cp.async.cg.shared.global [%0], [%1], 16;" :: "r"(dst), "l"(src) : "memory")
#define CP_COMMIT() asm volatile("cp.async.commit_group;" ::: "memory")
#define CP_WAIT(n)  asm volatile("cp.async.wait_group %0;" :: "n"(n) : "memory")

__device__ __forceinline__ void ldsm4(uint32_t* r, uint32_t addr) {
    asm volatile("ldmatrix.sync.aligned.m8n8.x4.shared.b16 {%0,%1,%2,%3}, [%4];"
                 : "=r"(r[0]), "=r"(r[1]), "=r"(r[2]), "=r"(r[3]) : "r"(addr));
}
__device__ __forceinline__ void mma16816(float* c, const uint32_t* a,
                                         uint32_t b0, uint32_t b1) {
    asm volatile("mma.sync.aligned.m16n8k16.row.col.f32.bf16.bf16.f32 "
                 "{%0,%1,%2,%3}, {%4,%5,%6,%7}, {%8,%9}, {%0,%1,%2,%3};"
                 : "+f"(c[0]), "+f"(c[1]), "+f"(c[2]), "+f"(c[3])
                 : "r"(a[0]), "r"(a[1]), "r"(a[2]), "r"(a[3]), "r"(b0), "r"(b1));
}
__device__ __forceinline__ uint32_t swz(uint32_t off) { return off ^ ((off >> 3) & 0x70); }

// ------------------------- fp32 -> bf16 hi/lo split --------------------------
__global__ __launch_bounds__(256) void split_kernel(const float* __restrict__ x,
                                                    __nv_bfloat16* __restrict__ hi,
                                                    __nv_bfloat16* __restrict__ lo,
                                                    int n4)
{
    int i = blockIdx.x * 256 + threadIdx.x;
    if (i >= n4) return;
    float4 v = ((const float4*)x)[i];
    __nv_bfloat16 h[4], l[4];
    float vv[4] = {v.x, v.y, v.z, v.w};
    #pragma unroll
    for (int j = 0; j < 4; j++) {
        h[j] = __float2bfloat16(vv[j]);
        l[j] = __float2bfloat16(vv[j] - __bfloat162float(h[j]));
    }
    ((uint2*)hi)[i] = *(uint2*)h;
    ((uint2*)lo)[i] = *(uint2*)l;
}

// ------------------------- mma.sync GEMM: C = A @ W^T + bias -----------------
// 128x128 tile, Kc=64, 256 threads (8 warps: 4 along M x 2 along N),
// 2-stage cp.async pipeline, 3 compensated bf16 passes.
#define GSM_TILE 16384
#define GSM_STAGE (4*GSM_TILE)            // Ahi, Alo, Bhi, Blo
#define GSM_TOTAL (2*GSM_STAGE)           // 131072
#define NSTAGE 16

// tile = 128 rows x 64 bf16 cols (128B rows), swizzled; 256 threads, 4 chunks ea.
__device__ __forceinline__ void load_tile(uint32_t sdst, const __nv_bfloat16* g,
                                          int row0, int kc0, int tid)
{
    const __nv_bfloat16* gp = g + (size_t)row0 * EMB + kc0;
    #pragma unroll
    for (int it = 0; it < 4; it++) {
        int lin = it * 256 + tid;
        int r = lin >> 3, cq = (lin & 7) << 3;
        uint32_t dst = sdst + swz((uint32_t)(r * 128 + cq * 2));
        CP16(dst, gp + (size_t)r * EMB + cq);
    }
}

__global__ __launch_bounds__(256) void tc_gemm(
    const __nv_bfloat16* __restrict__ Ahi, const __nv_bfloat16* __restrict__ Alo,
    const __nv_bfloat16* __restrict__ Bhi, const __nv_bfloat16* __restrict__ Blo,
    const float* __restrict__ bias, float* __restrict__ C, int mode)
{
    extern __shared__ char sm[];
    const uint32_t sbase = smem_u32(sm);
    const int tid  = threadIdx.x;
    const int wid  = tid >> 5, lane = tid & 31;
    const int wm   = wid >> 1, wn = wid & 1;      // warp grid 4x2
    const int bm   = blockIdx.y * 128, bn = blockIdx.x * 128;

    float acc[2][8][4];
    #pragma unroll
    for (int i = 0; i < 2; i++)
        #pragma unroll
        for (int j = 0; j < 8; j++)
            #pragma unroll
            for (int e = 0; e < 4; e++) acc[i][j][e] = 0.f;

    // ldmatrix per-lane offsets (within a tile)
    const int lrow = lane & 15;          // matrix row
    const int lchk = lane >> 4;          // which 16B chunk (k half)
    uint32_t offA[2], offB[4];
    #pragma unroll
    for (int i = 0; i < 2; i++) offA[i] = (uint32_t)((wm*32 + i*16 + lrow) * 128);
    #pragma unroll
    for (int j = 0; j < 4; j++) offB[j] = (uint32_t)((wn*64 + j*16 + lrow) * 128);

    // prefetch stage 0
    {
        uint32_t buf = sbase;
        load_tile(buf,              Ahi, bm, 0, tid);
        load_tile(buf + GSM_TILE,   Alo, bm, 0, tid);
        load_tile(buf + 2*GSM_TILE, Bhi, bn, 0, tid);
        load_tile(buf + 3*GSM_TILE, Blo, bn, 0, tid);
        CP_COMMIT();
    }

    for (int s = 0; s < NSTAGE; s++) {
        const uint32_t cbuf = sbase + (uint32_t)(s & 1) * GSM_STAGE;
        __syncthreads();                     // all warps done with buffer being refilled
        if (s + 1 < NSTAGE) {
            uint32_t buf = sbase + (uint32_t)((s + 1) & 1) * GSM_STAGE;
            int kc = (s + 1) * 64;
            load_tile(buf,              Ahi, bm, kc, tid);
            load_tile(buf + GSM_TILE,   Alo, bm, kc, tid);
            load_tile(buf + 2*GSM_TILE, Bhi, bn, kc, tid);
            load_tile(buf + 3*GSM_TILE, Blo, bn, kc, tid);
            CP_COMMIT();
            CP_WAIT(1);                      // stage s resident
        } else {
            CP_WAIT(0);
        }
        __syncthreads();

        // 3 compensated passes: (Ahi,Bhi), (Ahi,Blo), (Alo,Bhi)
        #pragma unroll
        for (int p = 0; p < 3; p++) {
            const uint32_t at = cbuf + ((p == 2) ? GSM_TILE : 0u);
            const uint32_t bt = cbuf + ((p == 1) ? 3u : 2u) * GSM_TILE;
            #pragma unroll
            for (int kk = 0; kk < 4; kk++) {
                const uint32_t kb = (uint32_t)((kk*2 + lchk) * 16);
                uint32_t a[2][4];
                #pragma unroll
                for (int i = 0; i < 2; i++)
                    ldsm4(a[i], at + swz(offA[i] + kb));
                #pragma unroll
                for (int j = 0; j < 4; j++) {
                    uint32_t b[4];
                    ldsm4(b, bt + swz(offB[j] + kb));
                    #pragma unroll
                    for (int i = 0; i < 2; i++) {
                        mma16816(acc[i][2*j],   a[i], b[0], b[2]);
                        mma16816(acc[i][2*j+1], a[i], b[1], b[3]);
                    }
                }
            }
        }
    }

    // epilogue: fragment -> gmem (+bias)
    const int grp = lane >> 2;           // row within m16
    const int cpo = (lane & 3) * 2;      // col pair offset within n8
    #pragma unroll
    for (int i = 0; i < 2; i++) {
        #pragma unroll
        for (int half = 0; half < 2; half++) {
            const int row = bm + wm*32 + i*16 + grp + half*8;
            const int bb = row >> 11, ss = row & 2047;
            #pragma unroll
            for (int j = 0; j < 8; j++) {
                const int col = bn + wn*64 + j*8 + cpo;
                const float v0 = acc[i][j][half*2]   + bias[col];
                const float v1 = acc[i][j][half*2+1] + bias[col+1];
                if (mode == 0) {
                    const int h = col >> 6, d = col & 63;
                    float* dst = &g_q[0]; // placeholder, unused
                    (void)dst;
                    float* base = C + (((size_t)bb * NH + h) * SEQ + ss) * HD + d;
                    base[0] = v0; base[1] = v1;   // d, d+1 stay in same head (col%64<=62)
                } else {
                    C[(size_t)row * EMB + col]     = v0;
                    C[(size_t)row * EMB + col + 1] = v1;
                }
            }
        }
    }
}

// ------------------------- RoPE ----------------------------------------------
__global__ __launch_bounds__(256) void rope_kernel()
{
    const int idx = blockIdx.x * 256 + threadIdx.x;
    const int total = BS_*NH*SEQ*32;
    if (idx >= total) return;
    const int d  = idx & 31;
    const int s  = (idx >> 5) & (SEQ-1);
    const int bh = idx >> 16;

    const float inv = exp2f(-(float)d * (13.287712379549449f / 32.0f));
    const float ang = (float)s * inv;
    float sn, cs;
    sincosf(ang, &sn, &cs);

    const size_t base = ((size_t)bh*SEQ + s)*HD;
    float q1 = g_q[base+d], q2 = g_q[base+d+32];
    g_q[base+d]    = q1*cs - q2*sn;
    g_q[base+d+32] = q2*cs + q1*sn;
    float k1 = g_k[base+d], k2 = g_k[base+d+32];
    g_k[base+d]    = k1*cs - k2*sn;
    g_k[base+d+32] = k2*cs + k1*sn;
}

// ------------------------- fp32 flash attention ------------------------------
#define ATS 68
#define ATT_SMEM (3 * 64 * ATS * 4)

extern __shared__ float att_smem[];

__global__ __launch_bounds__(256) void attn_kernel(float* __restrict__ out)
{
    float* Qs = att_smem;
    float* Ks = Qs + 64*ATS;
    float* Vs = Ks + 64*ATS;
    float* Ps = Ks;

    const int tid = threadIdx.x;
    const int tx  = tid & 15;
    const int ty  = tid >> 4;
    const int qt  = gridDim.x - 1 - blockIdx.x;
    const int bh  = blockIdx.y;
    const int b   = bh >> 4;
    const int h   = bh & 15;

    const float* Qg = g_q + (size_t)bh*SEQ*HD + (size_t)qt*64*HD;
    const float* Kg = g_k + (size_t)bh*SEQ*HD;
    const float* Vg = g_v + (size_t)bh*SEQ*HD;

    #pragma unroll
    for (int i = 0; i < 16; i++) {
        const int lin = tid + 256*i;
        const int r = lin >> 6, d = lin & 63;
        Qs[d*ATS + r] = Qg[r*HD + d];
    }

    float m[4], l[4], of[4][4];
    #pragma unroll
    for (int i = 0; i < 4; i++) {
        m[i] = -INFINITY; l[i] = 0.f;
        #pragma unroll
        for (int j = 0; j < 4; j++) of[i][j] = 0.f;
    }

    const float SCL = 0.125f * 1.44269504088896340736f;

    for (int j = 0; j <= qt; j++) {
        __syncthreads();
        #pragma unroll
        for (int i = 0; i < 16; i++) {
            const int lin = tid + 256*i;
            const int t = lin >> 6, d = lin & 63;
            Ks[d*ATS + t] = Kg[(j*64 + t)*HD + d];
            Vs[t*ATS + d] = Vg[(j*64 + t)*HD + d];
        }
        __syncthreads();

        float sf[4][4];
        #pragma unroll
        for (int i = 0; i < 4; i++)
            #pragma unroll
            for (int jj = 0; jj < 4; jj++) sf[i][jj] = 0.f;

        #pragma unroll 16
        for (int d = 0; d < 64; d++) {
            float4 qa = *(const float4*)&Qs[d*ATS + ty*4];
            float4 kb = *(const float4*)&Ks[d*ATS + tx*4];
            float ar[4] = {qa.x,qa.y,qa.z,qa.w};
            float br[4] = {kb.x,kb.y,kb.z,kb.w};
            #pragma unroll
            for (int i = 0; i < 4; i++)
                #pragma unroll
                for (int jj = 0; jj < 4; jj++)
                    sf[i][jj] += ar[i]*br[jj];
        }

        const bool diag = (j == qt);
        #pragma unroll
        for (int i = 0; i < 4; i++)
            #pragma unroll
            for (int jj = 0; jj < 4; jj++) {
                float s = sf[i][jj] * SCL;
                if (diag && (tx*4 + jj > ty*4 + i)) s = -INFINITY;
                sf[i][jj] = s;
            }

        #pragma unroll
        for (int i = 0; i < 4; i++) {
            float rmax = fmaxf(fmaxf(sf[i][0], sf[i][1]), fmaxf(sf[i][2], sf[i][3]));
            #pragma unroll
            for (int o = 8; o >= 1; o >>= 1)
                rmax = fmaxf(rmax, __shfl_xor_sync(0xffffffffu, rmax, o));
            const float mn = fmaxf(m[i], rmax);
            const float alpha = exp2f(m[i] - mn);
            float rs = 0.f;
            #pragma unroll
            for (int jj = 0; jj < 4; jj++) {
                const float p = exp2f(sf[i][jj] - mn);
                sf[i][jj] = p;
                rs += p;
            }
            #pragma unroll
            for (int o = 8; o >= 1; o >>= 1)
                rs += __shfl_xor_sync(0xffffffffu, rs, o);
            l[i] = l[i]*alpha + rs;
            m[i] = mn;
            #pragma unroll
            for (int jj = 0; jj < 4; jj++) of[i][jj] *= alpha;
        }

        __syncthreads();
        #pragma unroll
        for (int jj = 0; jj < 4; jj++) {
            float4 pv = make_float4(sf[0][jj], sf[1][jj], sf[2][jj], sf[3][jj]);
            *(float4*)&Ps[(tx*4 + jj)*ATS + ty*4] = pv;
        }
        __syncthreads();

        #pragma unroll 16
        for (int t = 0; t < 64; t++) {
            float4 pa = *(const float4*)&Ps[t*ATS + ty*4];
            float4 vb = *(const float4*)&Vs[t*ATS + tx*4];
            float pr[4] = {pa.x,pa.y,pa.z,pa.w};
            float vr[4] = {vb.x,vb.y,vb.z,vb.w};
            #pragma unroll
            for (int i = 0; i < 4; i++)
                #pragma unroll
                for (int jj = 0; jj < 4; jj++)
                    of[i][jj] += pr[i]*vr[jj];
        }
    }

    #pragma unroll
    for (int i = 0; i < 4; i++) {
        const int r = qt*64 + ty*4 + i;
        const float inv = 1.f / l[i];
        float4 o4 = make_float4(of[i][0]*inv, of[i][1]*inv, of[i][2]*inv, of[i][3]*inv);
        *(float4*)&out[((size_t)b*SEQ + r)*EMB + (size_t)h*64 + tx*4] = o4;
    }
}

// ---------------------------------------------------------------------------
extern "C" void kernel_launch(void* const* d_in, const int* in_sizes, int n_in,
                              void* d_out, int out_size)
{
    const float* query = (const float*)d_in[0];
    const float* key   = (const float*)d_in[1];
    const float* value = (const float*)d_in[2];
    const float* Wq    = (const float*)d_in[3];
    const float* bq    = (const float*)d_in[4];
    const float* Wk    = (const float*)d_in[5];
    const float* bk    = (const float*)d_in[6];
    const float* Wv    = (const float*)d_in[7];
    const float* bv    = (const float*)d_in[8];
    const float* Wo    = (const float*)d_in[9];
    const float* bo    = (const float*)d_in[10];

    float *pq, *pk, *pv, *pa;
    __nv_bfloat16 *ahi, *alo, *whi, *wlo;
    cudaGetSymbolAddress((void**)&pq, g_q);
    cudaGetSymbolAddress((void**)&pk, g_k);
    cudaGetSymbolAddress((void**)&pv, g_v);
    cudaGetSymbolAddress((void**)&pa, g_att);
    cudaGetSymbolAddress((void**)&ahi, g_ahi);
    cudaGetSymbolAddress((void**)&alo, g_alo);
    cudaGetSymbolAddress((void**)&whi, g_whi);
    cudaGetSymbolAddress((void**)&wlo, g_wlo);

    cudaFuncSetAttribute(tc_gemm,
                         cudaFuncAttributeMaxDynamicSharedMemorySize, GSM_TOTAL);
    cudaFuncSetAttribute(attn_kernel,
                         cudaFuncAttributeMaxDynamicSharedMemorySize, ATT_SMEM);

    const int n4in = MROWS*EMB/4;
    const int n4w  = EMB*EMB/4;
    dim3 gg(EMB/128, MROWS/128);    // 8 x 32

    split_kernel<<<n4in/256, 256>>>(query, ahi, alo, n4in);
    split_kernel<<<n4w/256, 256>>>(Wq, whi, wlo, n4w);
    tc_gemm<<<gg, 256, GSM_TOTAL>>>(ahi, alo, whi, wlo, bq, pq, 0);

    split_kernel<<<n4in/256, 256>>>(key, ahi, alo, n4in);
    split_kernel<<<n4w/256, 256>>>(Wk, whi, wlo, n4w);
    tc_gemm<<<gg, 256, GSM_TOTAL>>>(ahi, alo, whi, wlo, bk, pk, 0);

    split_kernel<<<n4in/256, 256>>>(value, ahi, alo, n4in);
    split_kernel<<<n4w/256, 256>>>(Wv, whi, wlo, n4w);
    tc_gemm<<<gg, 256, GSM_TOTAL>>>(ahi, alo, whi, wlo, bv, pv, 0);

    rope_kernel<<<(BS_*NH*SEQ*32)/256, 256>>>();

    attn_kernel<<<dim3(SEQ/64, BS_*NH), 256, ATT_SMEM>>>(pa);

    split_kernel<<<n4in/256, 256>>>(pa, ahi, alo, n4in);
    split_kernel<<<n4w/256, 256>>>(Wo, whi, wlo, n4w);
    tc_gemm<<<gg, 256, GSM_TOTAL>>>(ahi, alo, whi, wlo, bo, (float*)d_out, 1);
}

// round 6
// speedup vs baseline: 2.7090x; 1.5210x over previous
#include <cuda_runtime.h>
#include <cuda_bf16.h>
#include <math.h>
#include <stdint.h>

#define BS_  2
#define SEQ  2048
#define EMB  1024
#define NH   16
#define HD   64
#define MROWS (BS_*SEQ)   // 4096

// ------------------------- scratch (__device__ globals) ---------------------
__device__ __nv_bfloat16 g_qhi[(size_t)MROWS*EMB];  // [B,H,S,D] roped Q
__device__ __nv_bfloat16 g_qlo[(size_t)MROWS*EMB];
__device__ __nv_bfloat16 g_khi[(size_t)MROWS*EMB];  // [B,H,S,D] roped K
__device__ __nv_bfloat16 g_klo[(size_t)MROWS*EMB];
__device__ __nv_bfloat16 g_vhi[(size_t)MROWS*EMB];  // [B,H,S,D]
__device__ __nv_bfloat16 g_vlo[(size_t)MROWS*EMB];
__device__ __nv_bfloat16 g_ahi[(size_t)MROWS*EMB];  // activation hi/lo (gemm in)
__device__ __nv_bfloat16 g_alo[(size_t)MROWS*EMB];
__device__ __nv_bfloat16 g_whi[(size_t)EMB*EMB];
__device__ __nv_bfloat16 g_wlo[(size_t)EMB*EMB];
__device__ float g_cs[SEQ*32];                       // rope tables
__device__ float g_sn[SEQ*32];

// ------------------------- helpers ------------------------------------------
__device__ __forceinline__ uint32_t smem_u32(const void* p) {
    uint32_t a;
    asm("{ .reg .u64 t; cvta.to.shared.u64 t, %1; cvt.u32.u64 %0, t; }"
        : "=r"(a) : "l"(p));
    return a;
}
#define CP16(dst, src) \
    asm volatile("cp.async.cg.shared.global [%0], [%1], 16;" :: "r"(dst), "l"(src) : "memory")
#define CP_COMMIT() asm volatile("cp.async.commit_group;" ::: "memory")
#define CP_WAIT(n)  asm volatile("cp.async.wait_group %0;" :: "n"(n) : "memory")

__device__ __forceinline__ void ldsm4(uint32_t* r, uint32_t addr) {
    asm volatile("ldmatrix.sync.aligned.m8n8.x4.shared.b16 {%0,%1,%2,%3}, [%4];"
                 : "=r"(r[0]), "=r"(r[1]), "=r"(r[2]), "=r"(r[3]) : "r"(addr));
}
__device__ __forceinline__ void ldsm4t(uint32_t* r, uint32_t addr) {
    asm volatile("ldmatrix.sync.aligned.m8n8.x4.trans.shared.b16 {%0,%1,%2,%3}, [%4];"
                 : "=r"(r[0]), "=r"(r[1]), "=r"(r[2]), "=r"(r[3]) : "r"(addr));
}
__device__ __forceinline__ void mma16816(float* c, const uint32_t* a,
                                         uint32_t b0, uint32_t b1) {
    asm volatile("mma.sync.aligned.m16n8k16.row.col.f32.bf16.bf16.f32 "
                 "{%0,%1,%2,%3}, {%4,%5,%6,%7}, {%8,%9}, {%0,%1,%2,%3};"
                 : "+f"(c[0]), "+f"(c[1]), "+f"(c[2]), "+f"(c[3])
                 : "r"(a[0]), "r"(a[1]), "r"(a[2]), "r"(a[3]), "r"(b0), "r"(b1));
}
__device__ __forceinline__ uint32_t swz(uint32_t off) { return off ^ ((off >> 3) & 0x70); }
__device__ __forceinline__ uint32_t pack_bf(float lo, float hi) {
    uint32_t r;
    asm("cvt.rn.bf16x2.f32 %0, %1, %2;" : "=r"(r) : "f"(hi), "f"(lo));
    return r;
}

// ------------------------- rope table ----------------------------------------
__global__ __launch_bounds__(256) void table_kernel()
{
    int i = blockIdx.x * 256 + threadIdx.x;      // 65536
    int s = i >> 5, d = i & 31;
    float inv = exp2f(-(float)d * (13.287712379549449f / 32.0f));
    float sn, cs;
    sincosf((float)s * inv, &sn, &cs);
    g_cs[i] = cs; g_sn[i] = sn;
}

// ------------------------- fp32 -> bf16 hi/lo split --------------------------
__global__ __launch_bounds__(256) void split_kernel(const float* __restrict__ x,
                                                    __nv_bfloat16* __restrict__ hi,
                                                    __nv_bfloat16* __restrict__ lo,
                                                    int n4)
{
    int i = blockIdx.x * 256 + threadIdx.x;
    if (i >= n4) return;
    float4 v = ((const float4*)x)[i];
    __nv_bfloat16 h[4], l[4];
    float vv[4] = {v.x, v.y, v.z, v.w};
    #pragma unroll
    for (int j = 0; j < 4; j++) {
        h[j] = __float2bfloat16(vv[j]);
        l[j] = __float2bfloat16(vv[j] - __bfloat162float(h[j]));
    }
    ((uint2*)hi)[i] = *(uint2*)h;
    ((uint2*)lo)[i] = *(uint2*)l;
}

// ------------------------- mma.sync GEMM -------------------------------------
// modes: 1 = fp32 row-major; 2 = rope + hi/lo bf16 scatter [B,H,S,D];
//        3 = hi/lo bf16 scatter [B,H,S,D]
#define GSM_TILE 16384
#define GSM_STAGE (4*GSM_TILE)
#define GSM_TOTAL (2*GSM_STAGE)
#define NSTAGE 16

__device__ __forceinline__ void load_tile(uint32_t sdst, const __nv_bfloat16* g,
                                          int row0, int kc0, int tid)
{
    const __nv_bfloat16* gp = g + (size_t)row0 * EMB + kc0;
    #pragma unroll
    for (int it = 0; it < 4; it++) {
        int lin = it * 256 + tid;
        int r = lin >> 3, cq = (lin & 7) << 3;
        uint32_t dst = sdst + swz((uint32_t)(r * 128 + cq * 2));
        CP16(dst, gp + (size_t)r * EMB + cq);
    }
}

__global__ __launch_bounds__(256) void tc_gemm(
    const __nv_bfloat16* __restrict__ Ahi, const __nv_bfloat16* __restrict__ Alo,
    const __nv_bfloat16* __restrict__ Bhi, const __nv_bfloat16* __restrict__ Blo,
    const float* __restrict__ bias, void* __restrict__ Cp, void* __restrict__ C2p,
    int mode)
{
    extern __shared__ char sm[];
    const uint32_t sbase = smem_u32(sm);
    const int tid  = threadIdx.x;
    const int wid  = tid >> 5, lane = tid & 31;
    const int wm   = wid >> 1, wn = wid & 1;
    const int bm   = blockIdx.y * 128, bn = blockIdx.x * 128;

    float acc[2][8][4];
    #pragma unroll
    for (int i = 0; i < 2; i++)
        #pragma unroll
        for (int j = 0; j < 8; j++)
            #pragma unroll
            for (int e = 0; e < 4; e++) acc[i][j][e] = 0.f;

    const int lrow = lane & 15;
    const int lchk = lane >> 4;
    uint32_t offA[2], offB[4];
    #pragma unroll
    for (int i = 0; i < 2; i++) offA[i] = (uint32_t)((wm*32 + i*16 + lrow) * 128);
    #pragma unroll
    for (int j = 0; j < 4; j++) offB[j] = (uint32_t)((wn*64 + j*16 + lrow) * 128);

    {
        uint32_t buf = sbase;
        load_tile(buf,              Ahi, bm, 0, tid);
        load_tile(buf + GSM_TILE,   Alo, bm, 0, tid);
        load_tile(buf + 2*GSM_TILE, Bhi, bn, 0, tid);
        load_tile(buf + 3*GSM_TILE, Blo, bn, 0, tid);
        CP_COMMIT();
    }

    for (int s = 0; s < NSTAGE; s++) {
        const uint32_t cbuf = sbase + (uint32_t)(s & 1) * GSM_STAGE;
        __syncthreads();
        if (s + 1 < NSTAGE) {
            uint32_t buf = sbase + (uint32_t)((s + 1) & 1) * GSM_STAGE;
            int kc = (s + 1) * 64;
            load_tile(buf,              Ahi, bm, kc, tid);
            load_tile(buf + GSM_TILE,   Alo, bm, kc, tid);
            load_tile(buf + 2*GSM_TILE, Bhi, bn, kc, tid);
            load_tile(buf + 3*GSM_TILE, Blo, bn, kc, tid);
            CP_COMMIT();
            CP_WAIT(1);
        } else {
            CP_WAIT(0);
        }
        __syncthreads();

        #pragma unroll
        for (int p = 0; p < 3; p++) {
            const uint32_t at = cbuf + ((p == 2) ? GSM_TILE : 0u);
            const uint32_t bt = cbuf + ((p == 1) ? 3u : 2u) * GSM_TILE;
            #pragma unroll
            for (int kk = 0; kk < 4; kk++) {
                const uint32_t kb = (uint32_t)((kk*2 + lchk) * 16);
                uint32_t a[2][4];
                #pragma unroll
                for (int i = 0; i < 2; i++)
                    ldsm4(a[i], at + swz(offA[i] + kb));
                #pragma unroll
                for (int j = 0; j < 4; j++) {
                    uint32_t b[4];
                    ldsm4(b, bt + swz(offB[j] + kb));
                    #pragma unroll
                    for (int i = 0; i < 2; i++) {
                        mma16816(acc[i][2*j],   a[i], b[0], b[2]);
                        mma16816(acc[i][2*j+1], a[i], b[1], b[3]);
                    }
                }
            }
        }
    }

    const int grp = lane >> 2;
    const int cpo = (lane & 3) * 2;
    #pragma unroll
    for (int i = 0; i < 2; i++) {
        #pragma unroll
        for (int half = 0; half < 2; half++) {
            const int row = bm + wm*32 + i*16 + grp + half*8;
            const int bb = row >> 11, ss = row & 2047;
            if (mode == 1) {
                float* C = (float*)Cp;
                #pragma unroll
                for (int j = 0; j < 8; j++) {
                    const int col = bn + wn*64 + j*8 + cpo;
                    C[(size_t)row * EMB + col]     = acc[i][j][half*2]   + bias[col];
                    C[(size_t)row * EMB + col + 1] = acc[i][j][half*2+1] + bias[col+1];
                }
            } else if (mode == 2) {
                __nv_bfloat16* Ch = (__nv_bfloat16*)Cp;
                __nv_bfloat16* Cl = (__nv_bfloat16*)C2p;
                #pragma unroll
                for (int j = 0; j < 4; j++)
                    #pragma unroll
                    for (int e = 0; e < 2; e++) {
                        const int d   = j*8 + cpo + e;        // 0..31
                        const int col = bn + wn*64 + d;
                        const int hh  = col >> 6;
                        const float x1 = acc[i][j][half*2+e]   + bias[col];
                        const float x2 = acc[i][j+4][half*2+e] + bias[col+32];
                        const float cs = g_cs[ss*32 + d];
                        const float sn = g_sn[ss*32 + d];
                        const float y1 = x1*cs - x2*sn;
                        const float y2 = x2*cs + x1*sn;
                        const __nv_bfloat16 h1 = __float2bfloat16(y1);
                        const __nv_bfloat16 h2 = __float2bfloat16(y2);
                        const __nv_bfloat16 l1 = __float2bfloat16(y1 - __bfloat162float(h1));
                        const __nv_bfloat16 l2 = __float2bfloat16(y2 - __bfloat162float(h2));
                        const size_t base = (((size_t)bb*NH + hh)*SEQ + ss)*HD + d;
                        Ch[base]      = h1; Cl[base]      = l1;
                        Ch[base + 32] = h2; Cl[base + 32] = l2;
                    }
            } else {
                __nv_bfloat16* Ch = (__nv_bfloat16*)Cp;
                __nv_bfloat16* Cl = (__nv_bfloat16*)C2p;
                #pragma unroll
                for (int j = 0; j < 8; j++)
                    #pragma unroll
                    for (int e = 0; e < 2; e++) {
                        const int col = bn + wn*64 + j*8 + cpo + e;
                        const int hh = col >> 6, d = col & 63;
                        const float v = acc[i][j][half*2+e] + bias[col];
                        const __nv_bfloat16 hv = __float2bfloat16(v);
                        const __nv_bfloat16 lv = __float2bfloat16(v - __bfloat162float(hv));
                        const size_t base = (((size_t)bb*NH + hh)*SEQ + ss)*HD + d;
                        Ch[base] = hv; Cl[base] = lv;
                    }
            }
        }
    }
}

// ------------------------- tensor-core flash attention -----------------------
// Br=128, Bc=64, 256 threads (8 warps x 16 rows). hi/lo compensated QK and PV.
// smem: Qhi 0..16K, Qlo 16K..32K; stage s at 32K+s*32K: Khi,Klo,Vhi,Vlo (8K each)
#define ATT_TOTAL (32768 + 2*32768)

__device__ __forceinline__ void load_kv(uint32_t st,
    const __nv_bfloat16* kh, const __nv_bfloat16* kl,
    const __nv_bfloat16* vh, const __nv_bfloat16* vl, int t0, int tid)
{
    #pragma unroll
    for (int it = 0; it < 2; it++) {
        int lin = it * 256 + tid;
        int r = lin >> 3, c = (lin & 7) * 16;
        uint32_t so = swz((uint32_t)(r * 128 + c));
        size_t go = (size_t)(t0 + r) * 128 + c;
        CP16(st + so,          (const char*)kh + go);
        CP16(st + 8192 + so,   (const char*)kl + go);
        CP16(st + 16384 + so,  (const char*)vh + go);
        CP16(st + 24576 + so,  (const char*)vl + go);
    }
}

__global__ __launch_bounds__(256, 2) void attn_tc(
    const __nv_bfloat16* __restrict__ qhi, const __nv_bfloat16* __restrict__ qlo,
    const __nv_bfloat16* __restrict__ khi, const __nv_bfloat16* __restrict__ klo,
    const __nv_bfloat16* __restrict__ vhi, const __nv_bfloat16* __restrict__ vlo,
    __nv_bfloat16* __restrict__ ohi, __nv_bfloat16* __restrict__ olo)
{
    extern __shared__ char sm[];
    const uint32_t sb = smem_u32(sm);
    const int tid = threadIdx.x, wid = tid >> 5, lane = tid & 31;
    const int qt = gridDim.x - 1 - blockIdx.x;
    const int bh = blockIdx.y, b = bh >> 4, h = bh & 15;
    const size_t hb = (size_t)bh * SEQ * HD;

    const int lrow = lane & 15, lchk = lane >> 4;
    const int vsel = lane >> 3;
    const int vrow = (lane & 7) + ((vsel & 2) ? 8 : 0);
    const int vcol = (vsel & 1) ? 16 : 0;
    const int grp  = lane >> 2, cb = (lane & 3) * 2;

    // Q tiles (hi+lo), 128 rows x 128B
    {
        const char* qg  = (const char*)(qhi + hb + (size_t)qt * 128 * HD);
        const char* qg2 = (const char*)(qlo + hb + (size_t)qt * 128 * HD);
        #pragma unroll
        for (int it = 0; it < 4; it++) {
            int lin = it * 256 + tid;
            int r = lin >> 3, c = (lin & 7) * 16;
            uint32_t so = swz((uint32_t)(r * 128 + c));
            CP16(sb + so,         qg  + (size_t)r * 128 + c);
            CP16(sb + 16384 + so, qg2 + (size_t)r * 128 + c);
        }
    }
    load_kv(sb + 32768, khi + hb, klo + hb, vhi + hb, vlo + hb, 0, tid);
    CP_COMMIT();

    const int nit = 2 * qt + 2;
    float m0 = -INFINITY, m1 = -INFINITY, l0 = 0.f, l1 = 0.f;
    float oacc[8][4];
    #pragma unroll
    for (int jf = 0; jf < 8; jf++)
        #pragma unroll
        for (int e = 0; e < 4; e++) oacc[jf][e] = 0.f;

    const float SCL = 0.125f * 1.44269504088896340736f;
    const int rowg0 = qt*128 + wid*16 + grp;

    for (int j = 0; j < nit; j++) {
        const uint32_t st = sb + 32768 + (uint32_t)(j & 1) * 32768;
        __syncthreads();
        if (j + 1 < nit) {
            load_kv(sb + 32768 + (uint32_t)((j + 1) & 1) * 32768,
                    khi + hb, klo + hb, vhi + hb, vlo + hb, (j + 1) * 64, tid);
            CP_COMMIT();
            CP_WAIT(1);
        } else {
            CP_WAIT(0);
        }
        __syncthreads();

        // ---- S = Q K^T (3 compensated passes) ----
        float sacc[8][4];
        #pragma unroll
        for (int jf = 0; jf < 8; jf++)
            #pragma unroll
            for (int e = 0; e < 4; e++) sacc[jf][e] = 0.f;

        #pragma unroll
        for (int p = 0; p < 3; p++) {
            const uint32_t at = sb + ((p == 2) ? 16384u : 0u);
            const uint32_t bt = st + ((p == 1) ? 8192u : 0u);
            #pragma unroll
            for (int kk = 0; kk < 4; kk++) {
                const uint32_t kb = (uint32_t)((kk*2 + lchk) * 16);
                uint32_t a[4];
                ldsm4(a, at + swz((uint32_t)((wid*16 + lrow) * 128) + kb));
                #pragma unroll
                for (int jn = 0; jn < 4; jn++) {
                    uint32_t bv[4];
                    ldsm4(bv, bt + swz((uint32_t)((jn*16 + lrow) * 128) + kb));
                    mma16816(sacc[2*jn],   a, bv[0], bv[2]);
                    mma16816(sacc[2*jn+1], a, bv[1], bv[3]);
                }
            }
        }

        // scale + causal mask
        const bool diag = (j >= 2*qt);
        #pragma unroll
        for (int jf = 0; jf < 8; jf++)
            #pragma unroll
            for (int e = 0; e < 4; e++) {
                float s = sacc[jf][e] * SCL;
                if (diag) {
                    int colg = j*64 + jf*8 + cb + (e & 1);
                    int rowg = rowg0 + ((e >= 2) ? 8 : 0);
                    if (colg > rowg) s = -1e30f;
                }
                sacc[jf][e] = s;
            }

        // ---- online softmax ----
        float rmx0 = -3.0e30f, rmx1 = -3.0e30f;
        #pragma unroll
        for (int jf = 0; jf < 8; jf++) {
            rmx0 = fmaxf(rmx0, fmaxf(sacc[jf][0], sacc[jf][1]));
            rmx1 = fmaxf(rmx1, fmaxf(sacc[jf][2], sacc[jf][3]));
        }
        rmx0 = fmaxf(rmx0, __shfl_xor_sync(0xffffffffu, rmx0, 1));
        rmx0 = fmaxf(rmx0, __shfl_xor_sync(0xffffffffu, rmx0, 2));
        rmx1 = fmaxf(rmx1, __shfl_xor_sync(0xffffffffu, rmx1, 1));
        rmx1 = fmaxf(rmx1, __shfl_xor_sync(0xffffffffu, rmx1, 2));
        const float mn0 = fmaxf(m0, rmx0), mn1 = fmaxf(m1, rmx1);
        const float al0 = exp2f(m0 - mn0), al1 = exp2f(m1 - mn1);
        float rs0 = 0.f, rs1 = 0.f;
        #pragma unroll
        for (int jf = 0; jf < 8; jf++) {
            float p0 = exp2f(sacc[jf][0] - mn0); sacc[jf][0] = p0; rs0 += p0;
            float p1 = exp2f(sacc[jf][1] - mn0); sacc[jf][1] = p1; rs0 += p1;
            float p2 = exp2f(sacc[jf][2] - mn1); sacc[jf][2] = p2; rs1 += p2;
            float p3 = exp2f(sacc[jf][3] - mn1); sacc[jf][3] = p3; rs1 += p3;
        }
        rs0 += __shfl_xor_sync(0xffffffffu, rs0, 1);
        rs0 += __shfl_xor_sync(0xffffffffu, rs0, 2);
        rs1 += __shfl_xor_sync(0xffffffffu, rs1, 1);
        rs1 += __shfl_xor_sync(0xffffffffu, rs1, 2);
        l0 = l0*al0 + rs0; m0 = mn0;
        l1 = l1*al1 + rs1; m1 = mn1;
        #pragma unroll
        for (int jf = 0; jf < 8; jf++) {
            oacc[jf][0] *= al0; oacc[jf][1] *= al0;
            oacc[jf][2] *= al1; oacc[jf][3] *= al1;
        }

        // ---- O += P V (hi/lo compensated, P from registers) ----
        #pragma unroll
        for (int tc = 0; tc < 4; tc++) {
            // pack P fragments for k-chunk tc (cols 16tc..16tc+15 of S)
            float p00 = sacc[2*tc][0],   p01 = sacc[2*tc][1];
            float p10 = sacc[2*tc][2],   p11 = sacc[2*tc][3];
            float p20 = sacc[2*tc+1][0], p21 = sacc[2*tc+1][1];
            float p30 = sacc[2*tc+1][2], p31 = sacc[2*tc+1][3];
            __nv_bfloat16 h00 = __float2bfloat16(p00), h01 = __float2bfloat16(p01);
            __nv_bfloat16 h10 = __float2bfloat16(p10), h11 = __float2bfloat16(p11);
            __nv_bfloat16 h20 = __float2bfloat16(p20), h21 = __float2bfloat16(p21);
            __nv_bfloat16 h30 = __float2bfloat16(p30), h31 = __float2bfloat16(p31);
            uint32_t ph[4], pl[4];
            ph[0] = ((uint32_t)*(uint16_t*)&h01 << 16) | *(uint16_t*)&h00;
            ph[1] = ((uint32_t)*(uint16_t*)&h11 << 16) | *(uint16_t*)&h10;
            ph[2] = ((uint32_t)*(uint16_t*)&h21 << 16) | *(uint16_t*)&h20;
            ph[3] = ((uint32_t)*(uint16_t*)&h31 << 16) | *(uint16_t*)&h30;
            pl[0] = pack_bf(p00 - __bfloat162float(h00), p01 - __bfloat162float(h01));
            pl[1] = pack_bf(p10 - __bfloat162float(h10), p11 - __bfloat162float(h11));
            pl[2] = pack_bf(p20 - __bfloat162float(h20), p21 - __bfloat162float(h21));
            pl[3] = pack_bf(p30 - __bfloat162float(h30), p31 - __bfloat162float(h31));

            #pragma unroll
            for (int dn = 0; dn < 4; dn++) {
                const uint32_t ao = swz((uint32_t)((tc*16 + vrow) * 128 + dn*32 + vcol));
                uint32_t bh4[4], bl4[4];
                ldsm4t(bh4, st + 16384 + ao);
                ldsm4t(bl4, st + 24576 + ao);
                mma16816(oacc[2*dn],   ph, bh4[0], bh4[2]);
                mma16816(oacc[2*dn+1], ph, bh4[1], bh4[3]);
                mma16816(oacc[2*dn],   pl, bh4[0], bh4[2]);
                mma16816(oacc[2*dn+1], pl, bh4[1], bh4[3]);
                mma16816(oacc[2*dn],   ph, bl4[0], bl4[2]);
                mma16816(oacc[2*dn+1], ph, bl4[1], bl4[3]);
            }
        }
    }

    // epilogue: O/l -> bf16 hi/lo at [B,S,E]
    const float inv0 = 1.f / l0, inv1 = 1.f / l1;
    #pragma unroll
    for (int jf = 0; jf < 8; jf++)
        #pragma unroll
        for (int e = 0; e < 4; e++) {
            const float o = oacc[jf][e] * ((e >= 2) ? inv1 : inv0);
            const int d  = jf*8 + cb + (e & 1);
            const int sg = qt*128 + wid*16 + grp + ((e >= 2) ? 8 : 0);
            const __nv_bfloat16 hv = __float2bfloat16(o);
            const __nv_bfloat16 lv = __float2bfloat16(o - __bfloat162float(hv));
            const size_t off = ((size_t)b * SEQ + sg) * EMB + h*64 + d;
            ohi[off] = hv; olo[off] = lv;
        }
}

// ---------------------------------------------------------------------------
extern "C" void kernel_launch(void* const* d_in, const int* in_sizes, int n_in,
                              void* d_out, int out_size)
{
    const float* query = (const float*)d_in[0];
    const float* key   = (const float*)d_in[1];
    const float* value = (const float*)d_in[2];
    const float* Wq    = (const float*)d_in[3];
    const float* bq    = (const float*)d_in[4];
    const float* Wk    = (const float*)d_in[5];
    const float* bk    = (const float*)d_in[6];
    const float* Wv    = (const float*)d_in[7];
    const float* bv    = (const float*)d_in[8];
    const float* Wo    = (const float*)d_in[9];
    const float* bo    = (const float*)d_in[10];

    __nv_bfloat16 *qhi, *qlo, *khi, *klo, *vhi, *vlo, *ahi, *alo, *whi, *wlo;
    cudaGetSymbolAddress((void**)&qhi, g_qhi);
    cudaGetSymbolAddress((void**)&qlo, g_qlo);
    cudaGetSymbolAddress((void**)&khi, g_khi);
    cudaGetSymbolAddress((void**)&klo, g_klo);
    cudaGetSymbolAddress((void**)&vhi, g_vhi);
    cudaGetSymbolAddress((void**)&vlo, g_vlo);
    cudaGetSymbolAddress((void**)&ahi, g_ahi);
    cudaGetSymbolAddress((void**)&alo, g_alo);
    cudaGetSymbolAddress((void**)&whi, g_whi);
    cudaGetSymbolAddress((void**)&wlo, g_wlo);

    cudaFuncSetAttribute(tc_gemm,
                         cudaFuncAttributeMaxDynamicSharedMemorySize, GSM_TOTAL);
    cudaFuncSetAttribute(attn_tc,
                         cudaFuncAttributeMaxDynamicSharedMemorySize, ATT_TOTAL);

    const int n4in = MROWS*EMB/4;
    const int n4w  = EMB*EMB/4;
    dim3 gg(EMB/128, MROWS/128);

    table_kernel<<<SEQ*32/256, 256>>>();

    split_kernel<<<n4in/256, 256>>>(query, ahi, alo, n4in);
    split_kernel<<<n4w/256, 256>>>(Wq, whi, wlo, n4w);
    tc_gemm<<<gg, 256, GSM_TOTAL>>>(ahi, alo, whi, wlo, bq, qhi, qlo, 2);

    split_kernel<<<n4in/256, 256>>>(key, ahi, alo, n4in);
    split_kernel<<<n4w/256, 256>>>(Wk, whi, wlo, n4w);
    tc_gemm<<<gg, 256, GSM_TOTAL>>>(ahi, alo, whi, wlo, bk, khi, klo, 2);

    split_kernel<<<n4in/256, 256>>>(value, ahi, alo, n4in);
    split_kernel<<<n4w/256, 256>>>(Wv, whi, wlo, n4w);
    tc_gemm<<<gg, 256, GSM_TOTAL>>>(ahi, alo, whi, wlo, bv, vhi, vlo, 3);

    attn_tc<<<dim3(SEQ/128, BS_*NH), 256, ATT_TOTAL>>>(qhi, qlo, khi, klo,
                                                       vhi, vlo, ahi, alo);

    split_kernel<<<n4w/256, 256>>>(Wo, whi, wlo, n4w);
    tc_gemm<<<gg, 256, GSM_TOTAL>>>(ahi, alo, whi, wlo, bo, d_out, nullptr, 1);
}